// round 3
// baseline (speedup 1.0000x reference)
#include <cuda_runtime.h>
#include <stdint.h>

#define NB 32
#define NC 512
#define T_IN 1024
#define T_OUT 4096

// scratch: idx[b][t] = source column j  (512 KB, __device__ global per rules)
__device__ int g_idx[NB * T_OUT];

// ---------------------------------------------------------------------------
// Kernel 1: per-batch inclusive scan of durations + scatter of index map.
// One CTA per batch, 1024 threads (one per input position).
// Durations may be int32 or int64 (JAX x64-disabled ambiguity) — detect
// on-device from batch-0's row: int64 LE would have all odd 32-bit words == 0.
// ---------------------------------------------------------------------------
__global__ void build_idx_kernel(const int* __restrict__ dur32) {
    const int b = blockIdx.x;
    const int j = threadIdx.x;          // 0..1023

    // --- dtype detection (identical result in every CTA) ---
    __shared__ int s_not64;
    if (j == 0) s_not64 = 0;
    __syncthreads();
    // odd words of the first 2048 int32s (in-bounds for both dtypes)
    if (dur32[2 * j + 1] != 0) s_not64 = 1;   // benign race, all write 1
    __syncthreads();
    const bool is32 = (s_not64 != 0);

    const int d = is32 ? dur32[b * T_IN + j]
                       : dur32[(b * T_IN + j) * 2];   // low word of int64 LE

    const int lane = j & 31;
    const int warp = j >> 5;

    // warp inclusive scan
    int v = d;
#pragma unroll
    for (int o = 1; o < 32; o <<= 1) {
        int n = __shfl_up_sync(0xffffffffu, v, o);
        if (lane >= o) v += n;
    }

    __shared__ int wsum[32];
    if (lane == 31) wsum[warp] = v;
    __syncthreads();

    if (warp == 0) {
        int w = wsum[lane];
#pragma unroll
        for (int o = 1; o < 32; o <<= 1) {
            int n = __shfl_up_sync(0xffffffffu, w, o);
            if (lane >= o) w += n;
        }
        wsum[lane] = w;
    }
    __syncthreads();

    const int incl  = v + (warp ? wsum[warp - 1] : 0);  // cumsum[j]
    const int start = incl - d;                          // cumsum[j-1]

    int* __restrict__ row = g_idx + b * T_OUT;
    for (int t = start; t < incl; ++t) row[t] = j;
}

// ---------------------------------------------------------------------------
// Kernel 2: gather. One CTA = (batch, group of CPB channels).
// idx row staged in smem once per CTA, reused across CPB channels.
// float4 stores, 4 gather loads each (mostly L1 hits: mean duration = 4).
// ---------------------------------------------------------------------------
#define CPB 8
#define GATHER_THREADS 256

__global__ __launch_bounds__(GATHER_THREADS)
void gather_kernel(const float* __restrict__ enc, float* __restrict__ out) {
    const int groups_per_b = NC / CPB;              // 64
    const int b  = blockIdx.x / groups_per_b;
    const int cg = blockIdx.x % groups_per_b;

    __shared__ int sidx[T_OUT];
    {
        const int4* gi = (const int4*)(g_idx + b * T_OUT);
        int4*       si = (int4*)sidx;
        for (int i = threadIdx.x; i < T_OUT / 4; i += GATHER_THREADS)
            si[i] = gi[i];
    }
    __syncthreads();

    const int c0 = cg * CPB;
    const size_t base = (size_t)(b * NC + c0);

#pragma unroll
    for (int cc = 0; cc < CPB; ++cc) {
        const float* __restrict__ erow = enc + (base + cc) * T_IN;
        float4*      __restrict__ orow = (float4*)(out + (base + cc) * T_OUT);
        const int4*  __restrict__ si4  = (const int4*)sidx;

#pragma unroll
        for (int it = 0; it < (T_OUT / 4) / GATHER_THREADS; ++it) {
            const int t4 = it * GATHER_THREADS + threadIdx.x;
            const int4 id = si4[t4];
            float4 o;
            o.x = __ldg(erow + id.x);
            o.y = __ldg(erow + id.y);
            o.z = __ldg(erow + id.z);
            o.w = __ldg(erow + id.w);
            orow[t4] = o;
        }
    }
}

// ---------------------------------------------------------------------------
extern "C" void kernel_launch(void* const* d_in, const int* in_sizes, int n_in,
                              void* d_out, int out_size) {
    // metadata order should be (encodings, durations); detect by size anyway.
    const void* enc_p = d_in[0];
    const void* dur_p = d_in[1];
    if (n_in >= 2 && in_sizes[0] == NB * T_IN) {   // durations came first
        dur_p = d_in[0];
        enc_p = d_in[1];
    }
    const float* enc = (const float*)enc_p;
    const int*   dur = (const int*)dur_p;
    float* out = (float*)d_out;

    build_idx_kernel<<<NB, T_IN>>>(dur);
    gather_kernel<<<NB * (NC / CPB), GATHER_THREADS>>>(enc, out);
}

// round 10
// speedup vs baseline: 1.0853x; 1.0853x over previous
#include <cuda_runtime.h>
#include <stdint.h>

#define NB 32
#define NC 512
#define T_IN 1024
#define T_OUT 4096

#define CPB 8                    // channels per CTA
#define NT  256                  // threads per CTA
#define EPT (T_IN / NT)          // durations per thread in the scan = 4
#define NW  (NT / 32)            // warps per CTA = 8

// ---------------------------------------------------------------------------
// Fused kernel: each CTA = (batch, 8-channel group).
//   Phase A: scan this batch's durations (redundant across the 64 CTAs of a
//            batch, but the 8KB row is L2-resident and the cost hides under
//            memory latency) and scatter the run-length index map into smem.
//   Phase B: gather enc rows through the smem index map, streaming float4
//            stores (write-once data -> evict-first hint).
// Durations may be int32 or int64 (JAX x64 ambiguity) — detected on-device:
// int64 LE => all odd 32-bit words of batch-0's row are zero (durations<=4096).
// ---------------------------------------------------------------------------
__global__ __launch_bounds__(NT)
void length_regulate_kernel(const float* __restrict__ enc,
                            const int*   __restrict__ dur32,
                            float*       __restrict__ out) {
    const int groups_per_b = NC / CPB;              // 64
    const int b  = blockIdx.x / groups_per_b;
    const int cg = blockIdx.x % groups_per_b;
    const int tid = threadIdx.x;

    __shared__ int sidx[T_OUT];                     // 16 KB index map
    __shared__ int wsum[NW];                        // per-warp scan sums

    // ---- dtype detection: OR of odd words in first 2048 int32s ----
    int odd = 0;
#pragma unroll
    for (int i = 0; i < T_IN / NT; ++i)
        odd |= dur32[2 * (i * NT + tid) + 1];
    const bool is32 = __syncthreads_or(odd) != 0;

    // ---- Phase A: scan + scatter ----
    // thread handles durations j = tid*EPT .. tid*EPT+EPT-1
    int d[EPT];
    {
        const int j0 = tid * EPT;
        if (is32) {
#pragma unroll
            for (int k = 0; k < EPT; ++k) d[k] = dur32[b * T_IN + j0 + k];
        } else {
#pragma unroll
            for (int k = 0; k < EPT; ++k) d[k] = dur32[(b * T_IN + j0 + k) * 2];
        }
    }
    int tot = 0;
    int pre[EPT];                                   // exclusive prefix in-thread
#pragma unroll
    for (int k = 0; k < EPT; ++k) { pre[k] = tot; tot += d[k]; }

    const int lane = tid & 31;
    const int warp = tid >> 5;

    // warp inclusive scan of thread totals
    int incl = tot;
#pragma unroll
    for (int o = 1; o < 32; o <<= 1) {
        int n = __shfl_up_sync(0xffffffffu, incl, o);
        if (lane >= o) incl += n;
    }
    if (lane == 31) wsum[warp] = incl;
    __syncthreads();

    // scan the NW warp sums: ALL 32 lanes of warp 0 participate (full-mask
    // shfl with partial warp is UB / hangs on sm_103a — the R8 bug).
    if (warp == 0) {
        int w = (lane < NW) ? wsum[lane] : 0;
#pragma unroll
        for (int o = 1; o < 32; o <<= 1) {
            int n = __shfl_up_sync(0xffffffffu, w, o);
            if (lane >= o) w += n;
        }
        if (lane < NW) wsum[lane] = w;
    }
    __syncthreads();

    int base = (incl - tot) + (warp ? wsum[warp - 1] : 0);  // cum before j0

    // scatter runs: sidx[t] = j for t in [cum[j-1], cum[j])
    {
        const int j0 = tid * EPT;
#pragma unroll
        for (int k = 0; k < EPT; ++k) {
            const int s = base + pre[k];
            const int e = s + d[k];
            for (int t = s; t < e; ++t) sidx[t] = j0 + k;
        }
    }
    __syncthreads();

    // ---- Phase B: gather + streaming stores ----
    const int c0 = cg * CPB;
    const size_t rowbase = (size_t)(b * NC + c0);
    const int4* __restrict__ si4 = (const int4*)sidx;

#pragma unroll
    for (int cc = 0; cc < CPB; ++cc) {
        const float* __restrict__ erow = enc + (rowbase + cc) * T_IN;
        float4*      __restrict__ orow = (float4*)(out + (rowbase + cc) * T_OUT);

#pragma unroll
        for (int it = 0; it < (T_OUT / 4) / NT; ++it) {
            const int t4 = it * NT + tid;
            const int4 id = si4[t4];
            float4 o;
            o.x = __ldg(erow + id.x);
            o.y = __ldg(erow + id.y);
            o.z = __ldg(erow + id.z);
            o.w = __ldg(erow + id.w);
            __stcs(orow + t4, o);          // st.global.cs — write-once stream
        }
    }
}

// ---------------------------------------------------------------------------
extern "C" void kernel_launch(void* const* d_in, const int* in_sizes, int n_in,
                              void* d_out, int out_size) {
    const void* enc_p = d_in[0];
    const void* dur_p = d_in[1];
    if (n_in >= 2 && in_sizes[0] == NB * T_IN) {    // durations came first
        dur_p = d_in[0];
        enc_p = d_in[1];
    }
    length_regulate_kernel<<<NB * (NC / CPB), NT>>>(
        (const float*)enc_p, (const int*)dur_p, (float*)d_out);
}